// round 7
// baseline (speedup 1.0000x reference)
#include <cuda_runtime.h>
#include <math.h>

// Fixed shapes
#define BN 8192
#define DN 2048
#define TINV 10.0f            // 1/T, T = 0.1
#define NTHR 256              // 8 warps/block
#define WPB  (NTHR / 32)
#define NBLK 296              // 2 blocks per SM (148 SMs)
#define TOTW (NBLK * WPB)     // 2368 warps
#define NPAIR (BN / 2)        // 4096 row-pairs

// Scratch (device globals)
__device__ double g_partE[NBLK];
__device__ double g_partW[NBLK];
__device__ double g_partL[NBLK];
__device__ unsigned int g_count;

__device__ __forceinline__ float warp_sum(float v) {
    #pragma unroll
    for (int o = 16; o; o >>= 1) v += __shfl_xor_sync(0xffffffffu, v, o);
    return v;
}
__device__ __forceinline__ double warp_sum_d(double v) {
    #pragma unroll
    for (int o = 16; o; o >>= 1) v += __shfl_xor_sync(0xffffffffu, v, o);
    return v;
}

__global__ void __launch_bounds__(NTHR, 2)
fused_kernel(const float* __restrict__ embed,
             const float* __restrict__ ee,
             const float* __restrict__ labels,
             float* __restrict__ out) {
    __shared__ float4  sa[DN / 4];            // raw anchor, 8 KB
    __shared__ float   redf[WPB];
    __shared__ double  redE[WPB], redW[WPB], redL[WPB];
    __shared__ bool    s_last;

    const int tid  = threadIdx.x;
    const int warp = tid >> 5;
    const int lane = tid & 31;
    const int wg   = blockIdx.x * WPB + warp;

    // ---- Stage anchor into shared + ||e0||^2 partials; ONE sync. ----
    const float4* e4 = reinterpret_cast<const float4*>(embed);
    float na2p = 0.f;
    #pragma unroll
    for (int i = 0; i < (DN / 4) / NTHR; i++) {     // 2 iterations
        float4 v = e4[i * NTHR + tid];
        sa[i * NTHR + tid] = v;
        na2p = fmaf(v.x, v.x, na2p);
        na2p = fmaf(v.y, v.y, na2p);
        na2p = fmaf(v.z, v.z, na2p);
        na2p = fmaf(v.w, v.w, na2p);
    }
    na2p = warp_sum(na2p);
    if (lane == 0) redf[warp] = na2p;
    __syncthreads();

    float anorm2 = 0.f;
    #pragma unroll
    for (int i = 0; i < WPB; i++) anorm2 += redf[i];
    const float norm0 = sqrtf(anorm2);
    const float inv   = 1.0f / fmaxf(norm0, 1e-12f);     // F.normalize
    const float na    = fmaxf(norm0 * inv, 1e-6f);       // cos eps
    const float scale = TINV * inv / na;                 // neg = -scale*dot/nb

    // ---- Stream: TWO independent row streams per warp iteration. ----
    double E = 0.0, W = 0.0, L = 0.0;
    for (int pair = wg; pair < NPAIR; pair += TOTW) {
        const int r0 = pair * 2;
        const float4* x0 = reinterpret_cast<const float4*>(ee + (size_t)r0 * DN);
        const float4* x1 = reinterpret_cast<const float4*>(ee + (size_t)(r0 + 1) * DN);

        float dot0 = 0.f, n20 = 0.f, dot1 = 0.f, n21 = 0.f;
        #pragma unroll
        for (int i = 0; i < DN / (4 * 32); i++) {        // 16 iterations
            float4 xa = x0[i * 32 + lane];
            float4 xb = x1[i * 32 + lane];
            float4 a  = sa[i * 32 + lane];
            dot0 = fmaf(xa.x, a.x, dot0);
            dot0 = fmaf(xa.y, a.y, dot0);
            dot0 = fmaf(xa.z, a.z, dot0);
            dot0 = fmaf(xa.w, a.w, dot0);
            n20  = fmaf(xa.x, xa.x, n20);
            n20  = fmaf(xa.y, xa.y, n20);
            n20  = fmaf(xa.z, xa.z, n20);
            n20  = fmaf(xa.w, xa.w, n20);
            dot1 = fmaf(xb.x, a.x, dot1);
            dot1 = fmaf(xb.y, a.y, dot1);
            dot1 = fmaf(xb.z, a.z, dot1);
            dot1 = fmaf(xb.w, a.w, dot1);
            n21  = fmaf(xb.x, xb.x, n21);
            n21  = fmaf(xb.y, xb.y, n21);
            n21  = fmaf(xb.z, xb.z, n21);
            n21  = fmaf(xb.w, xb.w, n21);
        }
        dot0 = warp_sum(dot0);
        n20  = warp_sum(n20);
        dot1 = warp_sum(dot1);
        n21  = warp_sum(n21);

        if (lane == 0) {
            if (r0 != 0) {                        // row 0 excluded (j==i==0)
                float nb  = fmaxf(sqrtf(n20), 1e-6f);
                float neg = -scale * dot0 / nb;
                float lj  = labels[r0];
                E += (double)expf(neg);
                W += (double)lj * (double)neg;
                L += (double)lj;
            }
            {
                float nb  = fmaxf(sqrtf(n21), 1e-6f);
                float neg = -scale * dot1 / nb;
                float lj  = labels[r0 + 1];
                E += (double)expf(neg);
                W += (double)lj * (double)neg;
                L += (double)lj;
            }
        }
    }

    // ---- Block partials -> scratch ----
    if (lane == 0) { redE[warp] = E; redW[warp] = W; redL[warp] = L; }
    __syncthreads();
    if (warp == 0) {
        double e = (lane < WPB) ? redE[lane] : 0.0;
        double w = (lane < WPB) ? redW[lane] : 0.0;
        double l = (lane < WPB) ? redL[lane] : 0.0;
        e = warp_sum_d(e); w = warp_sum_d(w); l = warp_sum_d(l);
        if (lane == 0) {
            g_partE[blockIdx.x] = e;
            g_partW[blockIdx.x] = w;
            g_partL[blockIdx.x] = l;
            __threadfence();
            unsigned int c = atomicAdd(&g_count, 1u);
            s_last = (c == NBLK - 1);
        }
    }
    __syncthreads();

    // ---- Last block reduces ALL NBLK partials (strided) and finalizes ----
    if (s_last) {
        double e = 0.0, w = 0.0, l = 0.0;
        for (int idx = tid; idx < NBLK; idx += NTHR) {
            e += g_partE[idx]; w += g_partW[idx]; l += g_partL[idx];
        }
        e = warp_sum_d(e); w = warp_sum_d(w); l = warp_sum_d(l);
        if (lane == 0) { redE[warp] = e; redW[warp] = w; redL[warp] = l; }
        __syncthreads();
        if (tid == 0) {
            double Et = 0, Wt = 0, Lt = 0;
            #pragma unroll
            for (int i = 0; i < WPB; i++) { Et += redE[i]; Wt += redW[i]; Lt += redL[i]; }
            double l0   = (double)labels[0];
            double E0   = 1e-12 + Et;
            double C0   = 1e-12 + l0 * Lt;
            double logE = log(E0);
            double L0   = (l0 / C0) * (logE * Lt - Wt);
            out[0] = (float)(L0 / (double)BN);
            g_count = 0;                                  // reset for replay
        }
    }
}

extern "C" void kernel_launch(void* const* d_in, const int* in_sizes, int n_in,
                              void* d_out, int out_size) {
    const float* embed         = (const float*)d_in[0];
    const float* embed_enhance = (const float*)d_in[1];
    const float* labels        = (const float*)d_in[2];
    float* out = (float*)d_out;

    fused_kernel<<<NBLK, NTHR>>>(embed, embed_enhance, labels, out);
}